// round 2
// baseline (speedup 1.0000x reference)
#include <cuda_runtime.h>
#include <cuda_bf16.h>
#include <cstdint>

// ============================================================================
// Binary-sign GEMM: out[8192,1000] = sign(in[8192,12288]) @ sign(W[1000,12288])^T
// Stage 1: quantize both operands to bf16 {-1,0,+1} in __device__ scratch
//          (weight padded to 1024 rows with zeros -> no N bounds checks in GEMM)
// Stage 2: tcgen05 bf16 SS MMA, cg1, 128x256 tile, K staged 64 (SW128),
//          double-buffered SMEM, mbarrier-paced, TMEM accumulator.
//
// All tcgen05/TMEM code is guarded by __CUDA_ARCH_FEAT_SM103_ALL so the
// harness's base compute_103 gencode pass compiles (empty stubs); the real
// sm_103a SASS is what the driver loads.
// ============================================================================

#define KDIM    12288
#define M_ROWS  8192
#define N_COLS  1000
#define N_PAD   1024

#define TILE_M  128
#define TILE_N  256
#define TILE_K  64                      // bf16 cols per stage = 128 bytes/row (SW128)
#define NK      (KDIM / TILE_K)         // 192
#define THREADS 128

#define A_STAGE_BYTES (TILE_M * 128)    // 16 KB
#define B_STAGE_BYTES (TILE_N * 128)    // 32 KB
#define STAGE_BYTES   (A_STAGE_BYTES + B_STAGE_BYTES)   // 48 KB
#define SMEM_DYN_BYTES (2 * STAGE_BYTES + 1024)

// idesc kind::f16: F32 accum (1<<4), BF16 A (1<<7), BF16 B (1<<10),
// N=256 -> (256/8)<<17, M=128 -> (128/16)<<24
#define IDESC 0x8400490u

// Arch-accelerated feature gate: real code only on the sm_103a pass.
#if !defined(__CUDA_ARCH__) || defined(__CUDA_ARCH_FEAT_SM103_ALL)
#define HAS_TCGEN05 1
#else
#define HAS_TCGEN05 0
#endif

__device__ __align__(16) __nv_bfloat16 g_A[(size_t)M_ROWS * KDIM];
__device__ __align__(16) __nv_bfloat16 g_W[(size_t)N_PAD * KDIM];

// ---------------------------------------------------------------- PTX helpers
static __device__ __forceinline__ uint32_t smem_u32(const void* p) {
    return (uint32_t)__cvta_generic_to_shared(p);
}

static __device__ __forceinline__ bool elect_one() {
    uint32_t pred = 0;
#if HAS_TCGEN05
    asm volatile(
        "{\n\t.reg .pred p;\n\t"
        "elect.sync _|p, 0xFFFFFFFF;\n\t"
        "selp.b32 %0, 1, 0, p;\n\t}"
        : "=r"(pred));
#endif
    return pred != 0;
}

#define SWZ(off) ((off) ^ (((off) >> 3) & 0x70))

// SW128 K-major descriptor: layout=2, version=1 (Blackwell), SBO=64, LBO=1
static constexpr uint64_t DESC_BASE =
    (uint64_t(2) << 61) | (uint64_t(1) << 46) |
    (uint64_t(64) << 32) | (uint64_t(1) << 16);

static __device__ __forceinline__ uint64_t make_desc(uint32_t smem_addr) {
    return DESC_BASE | (uint64_t)((smem_addr >> 4) & 0x3FFF);
}

static __device__ __forceinline__ void mbar_init(uint32_t mbar, uint32_t count) {
    asm volatile("mbarrier.init.shared.b64 [%0], %1;" :: "r"(mbar), "r"(count) : "memory");
}

static __device__ __forceinline__ void mbar_wait(uint32_t mbar, uint32_t parity) {
    uint32_t done;
    asm volatile(
        "{\n\t.reg .pred p;\n\t"
        "mbarrier.try_wait.parity.acquire.cta.shared::cta.b64 p, [%1], %2;\n\t"
        "selp.b32 %0, 1, 0, p;\n\t}"
        : "=r"(done) : "r"(mbar), "r"(parity) : "memory");
    if (!done) {
        asm volatile(
            "{\n\t.reg .pred P1;\n\t"
            "WL_%=:\n\t"
            "mbarrier.try_wait.parity.acquire.cta.shared::cta.b64 P1, [%0], %1, 0x989680;\n\t"
            "@P1 bra.uni WD_%=;\n\t"
            "bra.uni WL_%=;\n\t"
            "WD_%=:\n\t}"
            :: "r"(mbar), "r"(parity) : "memory");
    }
}

static __device__ __forceinline__ void mma_f16_ss(uint32_t d_tmem, uint64_t a_desc,
                                                  uint64_t b_desc, uint32_t idesc,
                                                  bool accumulate) {
#if HAS_TCGEN05
    uint32_t en = accumulate ? 1u : 0u;
    asm volatile(
        "{\n\t.reg .pred p;\n\t"
        "setp.ne.u32 p, %5, 0;\n\t"
        "tcgen05.mma.cta_group::1.kind::f16 [%0], %1, %2, %3, {%4, %4, %4, %4}, p;\n\t}"
        :: "r"(d_tmem), "l"(a_desc), "l"(b_desc), "r"(idesc), "r"(0u), "r"(en)
        : "memory");
#endif
}

static __device__ __forceinline__ void tc_commit(uint32_t mbar) {
#if HAS_TCGEN05
    asm volatile(
        "tcgen05.commit.cta_group::1.mbarrier::arrive::one.shared::cluster.b64 [%0];"
        :: "r"(mbar) : "memory");
#endif
}

static __device__ __forceinline__ void ldtm_x32(uint32_t* r, uint32_t tmem_addr) {
#if HAS_TCGEN05
    asm volatile(
        "tcgen05.ld.sync.aligned.32x32b.x32.b32 "
        "{%0, %1, %2, %3, %4, %5, %6, %7, "
        " %8, %9, %10, %11, %12, %13, %14, %15, "
        " %16, %17, %18, %19, %20, %21, %22, %23, "
        " %24, %25, %26, %27, %28, %29, %30, %31}, [%32];"
        : "=r"(r[0]),  "=r"(r[1]),  "=r"(r[2]),  "=r"(r[3]),
          "=r"(r[4]),  "=r"(r[5]),  "=r"(r[6]),  "=r"(r[7]),
          "=r"(r[8]),  "=r"(r[9]),  "=r"(r[10]), "=r"(r[11]),
          "=r"(r[12]), "=r"(r[13]), "=r"(r[14]), "=r"(r[15]),
          "=r"(r[16]), "=r"(r[17]), "=r"(r[18]), "=r"(r[19]),
          "=r"(r[20]), "=r"(r[21]), "=r"(r[22]), "=r"(r[23]),
          "=r"(r[24]), "=r"(r[25]), "=r"(r[26]), "=r"(r[27]),
          "=r"(r[28]), "=r"(r[29]), "=r"(r[30]), "=r"(r[31])
        : "r"(tmem_addr));
    asm volatile("tcgen05.wait::ld.sync.aligned;" ::: "memory");
#endif
}

static __device__ __forceinline__ void sts128(uint32_t addr, uint4 v) {
    asm volatile("st.shared.v4.b32 [%0], {%1, %2, %3, %4};"
                 :: "r"(addr), "r"(v.x), "r"(v.y), "r"(v.z), "r"(v.w) : "memory");
}

// ---------------------------------------------------------------- quantization
static __device__ __forceinline__ uint32_t sgn_pack2(float lo, float hi) {
    uint32_t l = (lo > 0.f) ? 0x3F80u : ((lo < 0.f) ? 0xBF80u : 0u);
    uint32_t h = (hi > 0.f) ? 0x3F80u : ((hi < 0.f) ? 0xBF80u : 0u);
    return l | (h << 16);
}

__global__ void quantA_kernel(const float* __restrict__ in) {
    size_t i = (size_t)blockIdx.x * blockDim.x + threadIdx.x;
    const size_t n8 = (size_t)M_ROWS * KDIM / 8;
    if (i >= n8) return;
    const float4* p = (const float4*)in + i * 2;
    float4 a = p[0];
    float4 b = p[1];
    uint4 r;
    r.x = sgn_pack2(a.x, a.y);
    r.y = sgn_pack2(a.z, a.w);
    r.z = sgn_pack2(b.x, b.y);
    r.w = sgn_pack2(b.z, b.w);
    ((uint4*)g_A)[i] = r;
}

__global__ void quantW_kernel(const float* __restrict__ in) {
    size_t i = (size_t)blockIdx.x * blockDim.x + threadIdx.x;
    const size_t n8 = (size_t)N_PAD * KDIM / 8;
    if (i >= n8) return;
    size_t row = (i * 8) / KDIM;
    uint4 r = make_uint4(0u, 0u, 0u, 0u);
    if (row < N_COLS) {
        const float4* p = (const float4*)in + i * 2;
        float4 a = p[0];
        float4 b = p[1];
        r.x = sgn_pack2(a.x, a.y);
        r.y = sgn_pack2(a.z, a.w);
        r.z = sgn_pack2(b.x, b.y);
        r.w = sgn_pack2(b.z, b.w);
    }
    ((uint4*)g_W)[i] = r;
}

// ---------------------------------------------------------------- GEMM kernel
__global__ void __launch_bounds__(THREADS) bgemm_kernel(float* __restrict__ out) {
#if HAS_TCGEN05
    extern __shared__ char dsm[];
    __shared__ uint32_t s_tmem;
    __shared__ __align__(8) uint64_t s_mbar[2];

    const int tid = threadIdx.x;
    const int wid = tid >> 5;
    const int lid = tid & 31;
    const int ntile = blockIdx.x;                 // 0..3
    const int mtile = blockIdx.y;                 // 0..63
    const size_t mbase = (size_t)mtile * TILE_M;
    const size_t nbase = (size_t)ntile * TILE_N;

    // 1024-align the dynamic SMEM tile region (SW128 descriptor base requirement)
    uint32_t dyn_base = smem_u32(dsm);
    uint32_t pad = (1024u - (dyn_base & 1023u)) & 1023u;
    uint32_t tile_base = dyn_base + pad;

    if (wid == 0) {
        asm volatile(
            "tcgen05.alloc.cta_group::1.sync.aligned.shared::cta.b32 [%0], %1;"
            :: "r"(smem_u32(&s_tmem)), "r"((uint32_t)TILE_N) : "memory");
        asm volatile("tcgen05.relinquish_alloc_permit.cta_group::1.sync.aligned;");
    }
    if (tid == 0) {
        mbar_init(smem_u32(&s_mbar[0]), 1);
        mbar_init(smem_u32(&s_mbar[1]), 1);
    }
    __syncthreads();

    const uint32_t tmem = s_tmem;
    const uint32_t mb0 = smem_u32(&s_mbar[0]);
    const uint32_t mb1 = smem_u32(&s_mbar[1]);
    int ph0 = 0, ph1 = 0;

    const __nv_bfloat16* __restrict__ gA = g_A + mbase * KDIM;
    const __nv_bfloat16* __restrict__ gW = g_W + nbase * KDIM;

    for (int kt = 0; kt < NK; kt++) {
        const int b = kt & 1;
        const uint32_t mbar = b ? mb1 : mb0;
        if (kt >= 2) {
            // buffer b was consumed by MMAs committed at iteration kt-2
            if (b) { mbar_wait(mb1, ph1); ph1 ^= 1; }
            else   { mbar_wait(mb0, ph0); ph0 ^= 1; }
        }
        const uint32_t abuf = tile_base + (uint32_t)b * STAGE_BYTES;
        const uint32_t bbuf = abuf + A_STAGE_BYTES;
        const size_t kb = (size_t)kt * TILE_K;

        // A tile: 128 rows x 64 bf16 (128B rows). 1024 16B-chunks, 8/thread.
        // lane-layout: 8 consecutive threads cover one row (coalesced 128B).
        #pragma unroll
        for (int j = 0; j < 8; j++) {
            int idx = tid + j * 128;
            int row = idx >> 3, ch = idx & 7;
            uint4 v = *(const uint4*)(gA + (size_t)row * KDIM + kb + ch * 8);
            sts128(abuf + SWZ((uint32_t)(row * 128 + ch * 16)), v);
        }
        // B tile: 256 rows x 64 bf16. 2048 chunks, 16/thread.
        #pragma unroll
        for (int j = 0; j < 16; j++) {
            int idx = tid + j * 128;
            int row = idx >> 3, ch = idx & 7;
            uint4 v = *(const uint4*)(gW + (size_t)row * KDIM + kb + ch * 8);
            sts128(bbuf + SWZ((uint32_t)(row * 128 + ch * 16)), v);
        }
        // generic-proxy writes -> async-proxy (MMA) visibility
        asm volatile("fence.proxy.async.shared::cta;" ::: "memory");
        __syncthreads();

        if (wid == 0 && elect_one()) {
            uint64_t ad = make_desc(abuf);
            uint64_t bd = make_desc(bbuf);
            #pragma unroll
            for (int k = 0; k < 4; k++) {   // 4 x K=16 bf16 steps, +32B per step
                mma_f16_ss(tmem, ad + 2 * k, bd + 2 * k, IDESC, (kt | k) != 0);
            }
            tc_commit(mbar);
        }
    }

    // drain both buffers' final MMA commits
    mbar_wait(mb0, ph0);
    mbar_wait(mb1, ph1);
    asm volatile("tcgen05.fence::after_thread_sync;" ::: "memory");

    // epilogue: each warp reads its 32-lane TMEM subpartition, 32 cols at a time
    const int m = (int)mbase + wid * 32 + lid;
    float* __restrict__ orow = out + (size_t)m * N_COLS;
    for (int cb = 0; cb < TILE_N; cb += 32) {
        uint32_t r[32];
        ldtm_x32(r, tmem + cb);
        #pragma unroll
        for (int q = 0; q < 8; q++) {
            int col = (int)nbase + cb + q * 4;
            if (col + 4 <= N_COLS) {
                float4 v = make_float4(__uint_as_float(r[q * 4 + 0]),
                                       __uint_as_float(r[q * 4 + 1]),
                                       __uint_as_float(r[q * 4 + 2]),
                                       __uint_as_float(r[q * 4 + 3]));
                *(float4*)(orow + col) = v;
            }
        }
    }

    __syncthreads();
    if (wid == 0) {
        asm volatile("tcgen05.dealloc.cta_group::1.sync.aligned.b32 %0, %1;"
                     :: "r"(tmem), "r"((uint32_t)TILE_N));
    }
#endif // HAS_TCGEN05
}

// ---------------------------------------------------------------- launch
extern "C" void kernel_launch(void* const* d_in, const int* in_sizes, int n_in,
                              void* d_out, int out_size) {
    // robust input ordering: input is 8192*12288 elems, weight is 1000*12288
    const float* inp = (const float*)d_in[0];
    const float* wgt = (const float*)d_in[1];
    if (n_in >= 2 && in_sizes[0] != (int)((size_t)M_ROWS * KDIM)) {
        const float* t = inp; inp = wgt; wgt = t;
    }
    float* out = (float*)d_out;

    cudaFuncSetAttribute(bgemm_kernel,
                         cudaFuncAttributeMaxDynamicSharedMemorySize,
                         SMEM_DYN_BYTES);

    const size_t nA8 = (size_t)M_ROWS * KDIM / 8;     // 12,582,912
    const size_t nW8 = (size_t)N_PAD * KDIM / 8;      // 1,572,864
    quantA_kernel<<<(unsigned)((nA8 + 255) / 256), 256>>>(inp);
    quantW_kernel<<<(unsigned)((nW8 + 255) / 256), 256>>>(wgt);

    dim3 grid(N_PAD / TILE_N, M_ROWS / TILE_M);       // (4, 64)
    bgemm_kernel<<<grid, THREADS, SMEM_DYN_BYTES>>>(out);
}

// round 3
// speedup vs baseline: 1.9877x; 1.9877x over previous
#include <cuda_runtime.h>
#include <cuda_bf16.h>
#include <cstdint>

// ============================================================================
// Binary-sign GEMM: out[8192,1000] = sign(in[8192,12288]) @ sign(W[1000,12288])^T
// Stage 1: quantize operands to bf16 {-1,0,+1} in __device__ scratch
// Stage 2: tcgen05 bf16 SS MMA, 128x256 tile, cp.async 4-stage pipeline,
//          per-stage mbarrier backpressure, TMEM accumulator, 8-warp epilogue.
// tcgen05 bodies guarded for the harness's base compute_103 gencode pass.
// ============================================================================

#define KDIM    12288
#define M_ROWS  8192
#define N_COLS  1000
#define N_PAD   1024

#define TILE_M  128
#define TILE_N  256
#define TILE_K  64                      // 128 bytes/row (SW128)
#define NK      (KDIM / TILE_K)         // 192
#define THREADS 256
#define STAGES  4
#define PREF    (STAGES - 1)

#define A_STAGE_BYTES (TILE_M * 128)    // 16 KB
#define B_STAGE_BYTES (TILE_N * 128)    // 32 KB
#define STAGE_BYTES   (A_STAGE_BYTES + B_STAGE_BYTES)       // 48 KB
#define SMEM_DYN_BYTES (STAGES * STAGE_BYTES + 1024)        // ~193 KB

// idesc kind::f16: F32 accum, BF16 A/B, N=256, M=128
#define IDESC 0x8400490u

#if !defined(__CUDA_ARCH__) || defined(__CUDA_ARCH_FEAT_SM103_ALL)
#define HAS_TCGEN05 1
#else
#define HAS_TCGEN05 0
#endif

__device__ __align__(16) __nv_bfloat16 g_A[(size_t)M_ROWS * KDIM];
__device__ __align__(16) __nv_bfloat16 g_W[(size_t)N_PAD * KDIM];

// ---------------------------------------------------------------- PTX helpers
static __device__ __forceinline__ uint32_t smem_u32(const void* p) {
    return (uint32_t)__cvta_generic_to_shared(p);
}

static __device__ __forceinline__ bool elect_one() {
    uint32_t pred = 0;
#if HAS_TCGEN05
    asm volatile(
        "{\n\t.reg .pred p;\n\t"
        "elect.sync _|p, 0xFFFFFFFF;\n\t"
        "selp.b32 %0, 1, 0, p;\n\t}"
        : "=r"(pred));
#endif
    return pred != 0;
}

#define SWZ(off) ((off) ^ (((off) >> 3) & 0x70))

static constexpr uint64_t DESC_BASE =
    (uint64_t(2) << 61) | (uint64_t(1) << 46) |
    (uint64_t(64) << 32) | (uint64_t(1) << 16);

static __device__ __forceinline__ uint64_t make_desc(uint32_t smem_addr) {
    return DESC_BASE | (uint64_t)((smem_addr >> 4) & 0x3FFF);
}

static __device__ __forceinline__ void mbar_init(uint32_t mbar, uint32_t count) {
    asm volatile("mbarrier.init.shared.b64 [%0], %1;" :: "r"(mbar), "r"(count) : "memory");
}

static __device__ __forceinline__ void mbar_wait(uint32_t mbar, uint32_t parity) {
    uint32_t done;
    asm volatile(
        "{\n\t.reg .pred p;\n\t"
        "mbarrier.try_wait.parity.acquire.cta.shared::cta.b64 p, [%1], %2;\n\t"
        "selp.b32 %0, 1, 0, p;\n\t}"
        : "=r"(done) : "r"(mbar), "r"(parity) : "memory");
    if (!done) {
        asm volatile(
            "{\n\t.reg .pred P1;\n\t"
            "WL_%=:\n\t"
            "mbarrier.try_wait.parity.acquire.cta.shared::cta.b64 P1, [%0], %1, 0x989680;\n\t"
            "@P1 bra.uni WD_%=;\n\t"
            "bra.uni WL_%=;\n\t"
            "WD_%=:\n\t}"
            :: "r"(mbar), "r"(parity) : "memory");
    }
}

static __device__ __forceinline__ void mma_f16_ss(uint32_t d_tmem, uint64_t a_desc,
                                                  uint64_t b_desc, uint32_t idesc,
                                                  bool accumulate) {
#if HAS_TCGEN05
    uint32_t en = accumulate ? 1u : 0u;
    asm volatile(
        "{\n\t.reg .pred p;\n\t"
        "setp.ne.u32 p, %5, 0;\n\t"
        "tcgen05.mma.cta_group::1.kind::f16 [%0], %1, %2, %3, {%4, %4, %4, %4}, p;\n\t}"
        :: "r"(d_tmem), "l"(a_desc), "l"(b_desc), "r"(idesc), "r"(0u), "r"(en)
        : "memory");
#endif
}

static __device__ __forceinline__ void tc_commit(uint32_t mbar) {
#if HAS_TCGEN05
    asm volatile(
        "tcgen05.commit.cta_group::1.mbarrier::arrive::one.shared::cluster.b64 [%0];"
        :: "r"(mbar) : "memory");
#endif
}

static __device__ __forceinline__ void ldtm_x32(uint32_t* r, uint32_t tmem_addr) {
#if HAS_TCGEN05
    asm volatile(
        "tcgen05.ld.sync.aligned.32x32b.x32.b32 "
        "{%0, %1, %2, %3, %4, %5, %6, %7, "
        " %8, %9, %10, %11, %12, %13, %14, %15, "
        " %16, %17, %18, %19, %20, %21, %22, %23, "
        " %24, %25, %26, %27, %28, %29, %30, %31}, [%32];"
        : "=r"(r[0]),  "=r"(r[1]),  "=r"(r[2]),  "=r"(r[3]),
          "=r"(r[4]),  "=r"(r[5]),  "=r"(r[6]),  "=r"(r[7]),
          "=r"(r[8]),  "=r"(r[9]),  "=r"(r[10]), "=r"(r[11]),
          "=r"(r[12]), "=r"(r[13]), "=r"(r[14]), "=r"(r[15]),
          "=r"(r[16]), "=r"(r[17]), "=r"(r[18]), "=r"(r[19]),
          "=r"(r[20]), "=r"(r[21]), "=r"(r[22]), "=r"(r[23]),
          "=r"(r[24]), "=r"(r[25]), "=r"(r[26]), "=r"(r[27]),
          "=r"(r[28]), "=r"(r[29]), "=r"(r[30]), "=r"(r[31])
        : "r"(tmem_addr));
    asm volatile("tcgen05.wait::ld.sync.aligned;" ::: "memory");
#endif
}

static __device__ __forceinline__ void cp_async16(uint32_t smem_addr, const void* gptr) {
    asm volatile("cp.async.cg.shared.global [%0], [%1], 16;"
                 :: "r"(smem_addr), "l"(gptr) : "memory");
}
#define CP_COMMIT()  asm volatile("cp.async.commit_group;" ::: "memory")
#define CP_WAIT(n)   asm volatile("cp.async.wait_group %0;" :: "n"(n) : "memory")

// ---------------------------------------------------------------- quantization
static __device__ __forceinline__ uint32_t sgn_pack2(float lo, float hi) {
    uint32_t l = (lo > 0.f) ? 0x3F80u : ((lo < 0.f) ? 0xBF80u : 0u);
    uint32_t h = (hi > 0.f) ? 0x3F80u : ((hi < 0.f) ? 0xBF80u : 0u);
    return l | (h << 16);
}

__global__ void quantA_kernel(const float* __restrict__ in) {
    size_t i = (size_t)blockIdx.x * blockDim.x + threadIdx.x;
    const size_t n8 = (size_t)M_ROWS * KDIM / 8;
    if (i >= n8) return;
    const float4* p = (const float4*)in + i * 2;
    float4 a = p[0];
    float4 b = p[1];
    uint4 r;
    r.x = sgn_pack2(a.x, a.y);
    r.y = sgn_pack2(a.z, a.w);
    r.z = sgn_pack2(b.x, b.y);
    r.w = sgn_pack2(b.z, b.w);
    ((uint4*)g_A)[i] = r;
}

__global__ void quantW_kernel(const float* __restrict__ in) {
    size_t i = (size_t)blockIdx.x * blockDim.x + threadIdx.x;
    const size_t n8 = (size_t)N_PAD * KDIM / 8;
    if (i >= n8) return;
    size_t row = (i * 8) / KDIM;
    uint4 r = make_uint4(0u, 0u, 0u, 0u);
    if (row < N_COLS) {
        const float4* p = (const float4*)in + i * 2;
        float4 a = p[0];
        float4 b = p[1];
        r.x = sgn_pack2(a.x, a.y);
        r.y = sgn_pack2(a.z, a.w);
        r.z = sgn_pack2(b.x, b.y);
        r.w = sgn_pack2(b.z, b.w);
    }
    ((uint4*)g_W)[i] = r;
}

// ---------------------------------------------------------------- GEMM kernel
__global__ void __launch_bounds__(THREADS) bgemm_kernel(float* __restrict__ out) {
#if HAS_TCGEN05
    extern __shared__ char dsm[];
    __shared__ uint32_t s_tmem;
    __shared__ __align__(8) uint64_t s_mbar[STAGES];

    const int tid = threadIdx.x;
    const int wid = tid >> 5;
    const int lid = tid & 31;
    const int ntile = blockIdx.x;                 // 0..3
    const int mtile = blockIdx.y;                 // 0..63
    const size_t mbase = (size_t)mtile * TILE_M;
    const size_t nbase = (size_t)ntile * TILE_N;

    // 1024-align the SW128 tile region
    uint32_t dyn_base = smem_u32(dsm);
    uint32_t tile_base = dyn_base + ((1024u - (dyn_base & 1023u)) & 1023u);

    if (wid == 0) {
        asm volatile(
            "tcgen05.alloc.cta_group::1.sync.aligned.shared::cta.b32 [%0], %1;"
            :: "r"(smem_u32(&s_tmem)), "r"((uint32_t)TILE_N) : "memory");
        asm volatile("tcgen05.relinquish_alloc_permit.cta_group::1.sync.aligned;");
    }
    if (tid == 0) {
        #pragma unroll
        for (int s = 0; s < STAGES; s++) mbar_init(smem_u32(&s_mbar[s]), 1);
    }
    __syncthreads();

    const uint32_t tmem = s_tmem;
    uint32_t mb[STAGES];
    #pragma unroll
    for (int s = 0; s < STAGES; s++) mb[s] = smem_u32(&s_mbar[s]);

    const __nv_bfloat16* __restrict__ gA = g_A + mbase * KDIM;
    const __nv_bfloat16* __restrict__ gW = g_W + nbase * KDIM;

    // producer: issue one stage's loads via cp.async (256 threads, 12 chunks each)
    auto issue_loads = [&](int t) {
        const int s = t & (STAGES - 1);
        const uint32_t abuf = tile_base + (uint32_t)s * STAGE_BYTES;
        const uint32_t bbuf = abuf + A_STAGE_BYTES;
        const size_t kb = (size_t)t * TILE_K;
        #pragma unroll
        for (int j = 0; j < 4; j++) {           // A: 1024 chunks
            int idx = tid + j * THREADS;
            int row = idx >> 3, ch = idx & 7;
            cp_async16(abuf + SWZ((uint32_t)(row * 128 + ch * 16)),
                       gA + (size_t)row * KDIM + kb + ch * 8);
        }
        #pragma unroll
        for (int j = 0; j < 8; j++) {           // B: 2048 chunks
            int idx = tid + j * THREADS;
            int row = idx >> 3, ch = idx & 7;
            cp_async16(bbuf + SWZ((uint32_t)(row * 128 + ch * 16)),
                       gW + (size_t)row * KDIM + kb + ch * 8);
        }
    };

    // prologue: tiles 0..PREF-1
    #pragma unroll
    for (int t = 0; t < PREF; t++) {
        issue_loads(t);
        CP_COMMIT();
    }

    uint32_t phases = 0;
    for (int kt = 0; kt < NK; kt++) {
        const int t = kt + PREF;
        if (t < NK) {
            const int s = t & (STAGES - 1);
            if (t >= STAGES) {                  // buffer reuse: wait MMA of t-STAGES
                mbar_wait(mb[s], (phases >> s) & 1);
                phases ^= (1u << s);
            }
            issue_loads(t);
        }
        CP_COMMIT();
        CP_WAIT(PREF);                          // tile kt data resident
        asm volatile("fence.proxy.async.shared::cta;" ::: "memory");
        __syncthreads();

        if (wid == 0 && elect_one()) {
            const int s = kt & (STAGES - 1);
            const uint32_t abuf = tile_base + (uint32_t)s * STAGE_BYTES;
            uint64_t ad = make_desc(abuf);
            uint64_t bd = make_desc(abuf + A_STAGE_BYTES);
            #pragma unroll
            for (int k = 0; k < 4; k++) {       // 4 x K=16 steps, +32B each
                mma_f16_ss(tmem, ad + 2 * k, bd + 2 * k, IDESC, (kt | k) != 0);
            }
            tc_commit(mb[s]);
        }
    }

    // drain all outstanding MMA commits
    #pragma unroll
    for (int s = 0; s < STAGES; s++) mbar_wait(mb[s], (phases >> s) & 1);
    asm volatile("tcgen05.fence::after_thread_sync;" ::: "memory");

    // epilogue: 8 warps; warps 0-3 -> cols 0..127, warps 4-7 -> cols 128..255
    const int sub  = wid & 3;
    const int half = wid >> 2;
    const int m = (int)mbase + sub * 32 + lid;
    float* __restrict__ orow = out + (size_t)m * N_COLS;
    for (int cb = half * 128; cb < half * 128 + 128; cb += 32) {
        uint32_t r[32];
        ldtm_x32(r, tmem + cb);
        #pragma unroll
        for (int q = 0; q < 8; q++) {
            int col = (int)nbase + cb + q * 4;
            if (col + 4 <= N_COLS) {
                float4 v = make_float4(__uint_as_float(r[q * 4 + 0]),
                                       __uint_as_float(r[q * 4 + 1]),
                                       __uint_as_float(r[q * 4 + 2]),
                                       __uint_as_float(r[q * 4 + 3]));
                *(float4*)(orow + col) = v;
            }
        }
    }

    __syncthreads();
    if (wid == 0) {
        asm volatile("tcgen05.dealloc.cta_group::1.sync.aligned.b32 %0, %1;"
                     :: "r"(tmem), "r"((uint32_t)TILE_N));
    }
#endif // HAS_TCGEN05
}

// ---------------------------------------------------------------- launch
extern "C" void kernel_launch(void* const* d_in, const int* in_sizes, int n_in,
                              void* d_out, int out_size) {
    const float* inp = (const float*)d_in[0];
    const float* wgt = (const float*)d_in[1];
    if (n_in >= 2 && in_sizes[0] != (int)((size_t)M_ROWS * KDIM)) {
        const float* t = inp; inp = wgt; wgt = t;
    }
    float* out = (float*)d_out;

    cudaFuncSetAttribute(bgemm_kernel,
                         cudaFuncAttributeMaxDynamicSharedMemorySize,
                         SMEM_DYN_BYTES);

    const size_t nA8 = (size_t)M_ROWS * KDIM / 8;
    const size_t nW8 = (size_t)N_PAD * KDIM / 8;
    quantA_kernel<<<(unsigned)((nA8 + 255) / 256), 256>>>(inp);
    quantW_kernel<<<(unsigned)((nW8 + 255) / 256), 256>>>(wgt);

    dim3 grid(N_PAD / TILE_N, M_ROWS / TILE_M);       // (4, 64)
    bgemm_kernel<<<grid, THREADS, SMEM_DYN_BYTES>>>(out);
}

// round 5
// speedup vs baseline: 2.3613x; 1.1880x over previous
#include <cuda_runtime.h>
#include <cuda_bf16.h>
#include <cstdint>

// ============================================================================
// Binary-sign GEMM: out[8192,1000] = sign(in[8192,12288]) @ sign(W[1000,12288])^T
// Stage 1: quantize operands to bf16 {-1,0,+1} in __device__ scratch
// Stage 2: tcgen05 bf16 SS MMA, cta_group::2, 256x512 tile per CTA-pair
//          (two N=256 MMAs), cp.async 4-stage pipeline, cross-CTA full/free
//          mbarriers, TMEM accumulator (512 cols), 8-warp epilogue.
// tcgen05 bodies guarded for the harness's base compute_103 gencode pass.
// ============================================================================

#define KDIM    12288
#define M_ROWS  8192
#define N_COLS  1000
#define N_PAD   1024

#define TILE_MP 256                     // per cluster pair
#define TILE_NP 512                     // per cluster pair (2 x N=256 MMA)
#define TILE_K  64                      // 128 bytes/row (SW128)
#define NK      (KDIM / TILE_K)         // 192
#define THREADS 256
#define STAGES  4
#define PREF    (STAGES - 1)

// per-CTA stage: A slice 128x64 (16KB) + B slices 2x128x64 (32KB)
#define A_STAGE_BYTES (128 * 128)
#define B_STAGE_BYTES (256 * 128)
#define STAGE_BYTES   (A_STAGE_BYTES + B_STAGE_BYTES)       // 48 KB
#define SMEM_DYN_BYTES (STAGES * STAGE_BYTES + 1024)        // ~193 KB

// idesc kind::f16 cg2: F32 accum (1<<4), BF16 A (1<<7), BF16 B (1<<10),
// N=256 -> (256/8)<<17, M=256 -> (256/16)<<24
#define IDESC 0x10400490u

#if !defined(__CUDA_ARCH__) || defined(__CUDA_ARCH_FEAT_SM103_ALL)
#define HAS_TCGEN05 1
#else
#define HAS_TCGEN05 0
#endif

__device__ __align__(16) __nv_bfloat16 g_A[(size_t)M_ROWS * KDIM];
__device__ __align__(16) __nv_bfloat16 g_W[(size_t)N_PAD * KDIM];

// ---------------------------------------------------------------- PTX helpers
static __device__ __forceinline__ uint32_t smem_u32(const void* p) {
    return (uint32_t)__cvta_generic_to_shared(p);
}

static __device__ __forceinline__ bool elect_one() {
    uint32_t pred = 0;
#if HAS_TCGEN05
    asm volatile(
        "{\n\t.reg .pred p;\n\t"
        "elect.sync _|p, 0xFFFFFFFF;\n\t"
        "selp.b32 %0, 1, 0, p;\n\t}"
        : "=r"(pred));
#endif
    return pred != 0;
}

#define SWZ(off) ((off) ^ (((off) >> 3) & 0x70))

static constexpr uint64_t DESC_BASE =
    (uint64_t(2) << 61) | (uint64_t(1) << 46) |
    (uint64_t(64) << 32) | (uint64_t(1) << 16);

static __device__ __forceinline__ uint64_t make_desc(uint32_t smem_addr) {
    return DESC_BASE | (uint64_t)((smem_addr >> 4) & 0x3FFF);
}

static __device__ __forceinline__ void mbar_init(uint32_t mbar, uint32_t count) {
    asm volatile("mbarrier.init.shared.b64 [%0], %1;" :: "r"(mbar), "r"(count) : "memory");
}

static __device__ __forceinline__ void mbar_wait(uint32_t mbar, uint32_t parity) {
    uint32_t done;
    asm volatile(
        "{\n\t.reg .pred p;\n\t"
        "mbarrier.try_wait.parity.acquire.cta.shared::cta.b64 p, [%1], %2;\n\t"
        "selp.b32 %0, 1, 0, p;\n\t}"
        : "=r"(done) : "r"(mbar), "r"(parity) : "memory");
    if (!done) {
        asm volatile(
            "{\n\t.reg .pred P1;\n\t"
            "WL_%=:\n\t"
            "mbarrier.try_wait.parity.acquire.cta.shared::cta.b64 P1, [%0], %1, 0x989680;\n\t"
            "@P1 bra.uni WD_%=;\n\t"
            "bra.uni WL_%=;\n\t"
            "WD_%=:\n\t}"
            :: "r"(mbar), "r"(parity) : "memory");
    }
}

// arrive on the cluster-leader's (rank 0) barrier at the same SMEM offset
static __device__ __forceinline__ void mbar_arrive_leader(uint32_t local_addr) {
#if HAS_TCGEN05
    asm volatile(
        "{\n\t.reg .b32 r;\n\t"
        "mapa.shared::cluster.u32 r, %0, 0;\n\t"
        "mbarrier.arrive.shared::cluster.b64 _, [r];\n\t}"
        :: "r"(local_addr) : "memory");
#endif
}

static __device__ __forceinline__ void mma_f16_ss_cg2(uint32_t d_tmem, uint64_t a_desc,
                                                      uint64_t b_desc, uint32_t idesc,
                                                      bool accumulate) {
#if HAS_TCGEN05
    uint32_t en = accumulate ? 1u : 0u;
    asm volatile(
        "{\n\t.reg .pred p;\n\t"
        "setp.ne.u32 p, %5, 0;\n\t"
        "tcgen05.mma.cta_group::2.kind::f16 [%0], %1, %2, %3, "
        "{%4, %4, %4, %4, %4, %4, %4, %4}, p;\n\t}"
        :: "r"(d_tmem), "l"(a_desc), "l"(b_desc), "r"(idesc), "r"(0u), "r"(en)
        : "memory");
#endif
}

static __device__ __forceinline__ void tc_commit_mc(uint32_t mbar) {
#if HAS_TCGEN05
    asm volatile(
        "tcgen05.commit.cta_group::2.mbarrier::arrive::one.shared::cluster"
        ".multicast::cluster.b64 [%0], %1;"
        :: "r"(mbar), "h"((uint16_t)0x3) : "memory");
#endif
}

static __device__ __forceinline__ void ldtm_x32(uint32_t* r, uint32_t tmem_addr) {
#if HAS_TCGEN05
    asm volatile(
        "tcgen05.ld.sync.aligned.32x32b.x32.b32 "
        "{%0, %1, %2, %3, %4, %5, %6, %7, "
        " %8, %9, %10, %11, %12, %13, %14, %15, "
        " %16, %17, %18, %19, %20, %21, %22, %23, "
        " %24, %25, %26, %27, %28, %29, %30, %31}, [%32];"
        : "=r"(r[0]),  "=r"(r[1]),  "=r"(r[2]),  "=r"(r[3]),
          "=r"(r[4]),  "=r"(r[5]),  "=r"(r[6]),  "=r"(r[7]),
          "=r"(r[8]),  "=r"(r[9]),  "=r"(r[10]), "=r"(r[11]),
          "=r"(r[12]), "=r"(r[13]), "=r"(r[14]), "=r"(r[15]),
          "=r"(r[16]), "=r"(r[17]), "=r"(r[18]), "=r"(r[19]),
          "=r"(r[20]), "=r"(r[21]), "=r"(r[22]), "=r"(r[23]),
          "=r"(r[24]), "=r"(r[25]), "=r"(r[26]), "=r"(r[27]),
          "=r"(r[28]), "=r"(r[29]), "=r"(r[30]), "=r"(r[31])
        : "r"(tmem_addr));
    asm volatile("tcgen05.wait::ld.sync.aligned;" ::: "memory");
#endif
}

static __device__ __forceinline__ void cp_async16(uint32_t smem_addr, const void* gptr) {
    asm volatile("cp.async.cg.shared.global [%0], [%1], 16;"
                 :: "r"(smem_addr), "l"(gptr) : "memory");
}
#define CP_COMMIT()  asm volatile("cp.async.commit_group;" ::: "memory")
#define CP_WAIT(n)   asm volatile("cp.async.wait_group %0;" :: "n"(n) : "memory")
#define CLUSTER_ARRIVE() asm volatile("barrier.cluster.arrive.aligned;" ::: "memory")
#define CLUSTER_WAIT()   asm volatile("barrier.cluster.wait.aligned;" ::: "memory")

// ---------------------------------------------------------------- quantization
static __device__ __forceinline__ uint32_t sgn_pack2(float lo, float hi) {
    uint32_t l = (lo > 0.f) ? 0x3F80u : ((lo < 0.f) ? 0xBF80u : 0u);
    uint32_t h = (hi > 0.f) ? 0x3F80u : ((hi < 0.f) ? 0xBF80u : 0u);
    return l | (h << 16);
}

__global__ void quantA_kernel(const float* __restrict__ in) {
    size_t i = (size_t)blockIdx.x * blockDim.x + threadIdx.x;
    const size_t n8 = (size_t)M_ROWS * KDIM / 8;
    if (i >= n8) return;
    const float4* p = (const float4*)in + i * 2;
    float4 a = p[0];
    float4 b = p[1];
    uint4 r;
    r.x = sgn_pack2(a.x, a.y);
    r.y = sgn_pack2(a.z, a.w);
    r.z = sgn_pack2(b.x, b.y);
    r.w = sgn_pack2(b.z, b.w);
    ((uint4*)g_A)[i] = r;
}

__global__ void quantW_kernel(const float* __restrict__ in) {
    size_t i = (size_t)blockIdx.x * blockDim.x + threadIdx.x;
    const size_t n8 = (size_t)N_PAD * KDIM / 8;
    if (i >= n8) return;
    size_t row = (i * 8) / KDIM;
    uint4 r = make_uint4(0u, 0u, 0u, 0u);
    if (row < N_COLS) {
        const float4* p = (const float4*)in + i * 2;
        float4 a = p[0];
        float4 b = p[1];
        r.x = sgn_pack2(a.x, a.y);
        r.y = sgn_pack2(a.z, a.w);
        r.z = sgn_pack2(b.x, b.y);
        r.w = sgn_pack2(b.z, b.w);
    }
    ((uint4*)g_W)[i] = r;
}

// ---------------------------------------------------------------- GEMM kernel
__global__ void __launch_bounds__(THREADS) __cluster_dims__(2, 1, 1)
bgemm_kernel(float* __restrict__ out) {
#if HAS_TCGEN05
    extern __shared__ char dsm[];
    __shared__ uint32_t s_tmem;
    __shared__ __align__(8) uint64_t s_full[STAGES];   // leader-side: data ready (count 2)
    __shared__ __align__(8) uint64_t s_free[STAGES];   // both: buffer consumed (count 1)

    const int tid = threadIdx.x;
    const int wid = tid >> 5;
    const int lid = tid & 31;
    const int rank  = (int)(blockIdx.x & 1);      // cluster rank (cluster dim x=2)
    const int ntile = (int)(blockIdx.x >> 1);     // 0..1
    const int mtile = (int)blockIdx.y;            // 0..31
    const size_t mrow  = (size_t)mtile * TILE_MP + (size_t)rank * 128;  // this CTA's A rows
    const size_t nbase = (size_t)ntile * TILE_NP;

    uint32_t dyn_base = smem_u32(dsm);
    uint32_t tile_base = dyn_base + ((1024u - (dyn_base & 1023u)) & 1023u);

    if (wid == 0) {
        asm volatile(
            "tcgen05.alloc.cta_group::2.sync.aligned.shared::cta.b32 [%0], %1;"
            :: "r"(smem_u32(&s_tmem)), "r"(512u) : "memory");
        asm volatile("tcgen05.relinquish_alloc_permit.cta_group::2.sync.aligned;");
    }
    if (tid == 0) {
        #pragma unroll
        for (int s = 0; s < STAGES; s++) {
            mbar_init(smem_u32(&s_full[s]), 2);   // one arrive per CTA
            mbar_init(smem_u32(&s_free[s]), 1);   // multicast commit
        }
    }
    __syncthreads();
    // peer mbarriers must be initialized before any cross-CTA arrive / commit
    CLUSTER_ARRIVE();
    CLUSTER_WAIT();

    const uint32_t tmem = s_tmem;
    uint32_t full_[STAGES], free_[STAGES];
    #pragma unroll
    for (int s = 0; s < STAGES; s++) {
        full_[s] = smem_u32(&s_full[s]);
        free_[s] = smem_u32(&s_free[s]);
    }

    const __nv_bfloat16* __restrict__ gA = g_A + mrow * KDIM;
    // B: this CTA holds W rows {nbase + rank*128 + r + (r & 128) : r in [0,256)}
    const __nv_bfloat16* __restrict__ gW = g_W + (nbase + (size_t)rank * 128) * KDIM;

    auto issue_loads = [&](int t) {
        const int s = t & (STAGES - 1);
        const uint32_t abuf = tile_base + (uint32_t)s * STAGE_BYTES;
        const uint32_t bbuf = abuf + A_STAGE_BYTES;
        const size_t kb = (size_t)t * TILE_K;
        #pragma unroll
        for (int j = 0; j < 4; j++) {            // A: 1024 x 16B chunks
            int idx = tid + j * THREADS;
            int row = idx >> 3, ch = idx & 7;
            cp_async16(abuf + SWZ((uint32_t)(row * 128 + ch * 16)),
                       gA + (size_t)row * KDIM + kb + ch * 8);
        }
        #pragma unroll
        for (int j = 0; j < 8; j++) {            // B: 2048 x 16B chunks (2 halves)
            int idx = tid + j * THREADS;
            int row = idx >> 3, ch = idx & 7;
            int grow = row + (row & 128);        // rows [0,128)->half0, [128,256)->half1(+128)
            cp_async16(bbuf + SWZ((uint32_t)(row * 128 + ch * 16)),
                       gW + (size_t)grow * KDIM + kb + ch * 8);
        }
    };

    #pragma unroll
    for (int t = 0; t < PREF; t++) {
        issue_loads(t);
        CP_COMMIT();
    }

    uint32_t free_ph = 0;                         // producer-side free phases
    uint32_t full_ph = 0;                         // leader-side full phases
    for (int kt = 0; kt < NK; kt++) {
        const int t = kt + PREF;
        if (t < NK) {
            const int s = t & (STAGES - 1);
            if (t >= STAGES) {                    // wait MMA of tile t-STAGES
                mbar_wait(free_[s], (free_ph >> s) & 1);
                free_ph ^= (1u << s);
            }
            issue_loads(t);
        }
        CP_COMMIT();
        CP_WAIT(PREF);                            // tile kt resident locally
        asm volatile("fence.proxy.async.shared::cta;" ::: "memory");
        __syncthreads();

        const int sk = kt & (STAGES - 1);
        if (tid == 0) mbar_arrive_leader(full_[sk]);   // both CTAs signal leader

        if (rank == 0 && wid == 0 && elect_one()) {
            mbar_wait(full_[sk], (full_ph >> sk) & 1);  // both CTAs' data ready
            full_ph ^= (1u << sk);
            const uint32_t abuf = tile_base + (uint32_t)sk * STAGE_BYTES;
            uint64_t ad  = make_desc(abuf);
            uint64_t bd0 = make_desc(abuf + A_STAGE_BYTES);
            uint64_t bd1 = make_desc(abuf + A_STAGE_BYTES + 16384);
            #pragma unroll
            for (int k = 0; k < 4; k++) {         // 4 x K=16 steps, +32B each
                mma_f16_ss_cg2(tmem,       ad + 2 * k, bd0 + 2 * k, IDESC, (kt | k) != 0);
                mma_f16_ss_cg2(tmem + 256, ad + 2 * k, bd1 + 2 * k, IDESC, (kt | k) != 0);
            }
            tc_commit_mc(free_[sk]);              // arrives on both CTAs
        }
    }

    // drain: last STAGES tiles' commits (multicast reached both CTAs)
    #pragma unroll
    for (int s = 0; s < STAGES; s++) mbar_wait(free_[s], (free_ph >> s) & 1);
    asm volatile("tcgen05.fence::after_thread_sync;" ::: "memory");

    // epilogue: 8 warps; rows (wid&3)*32, col-half (wid>>2)*256; own TMEM slice
    const int sub  = wid & 3;
    const int half = wid >> 2;
    const int m = (int)mrow + sub * 32 + lid;
    float* __restrict__ orow = out + (size_t)m * N_COLS;
    for (int cb = half * 256; cb < half * 256 + 256; cb += 32) {
        uint32_t r[32];
        ldtm_x32(r, tmem + cb);
        #pragma unroll
        for (int q = 0; q < 8; q++) {
            int col = (int)nbase + cb + q * 4;
            if (col + 4 <= N_COLS) {
                float4 v = make_float4(__uint_as_float(r[q * 4 + 0]),
                                       __uint_as_float(r[q * 4 + 1]),
                                       __uint_as_float(r[q * 4 + 2]),
                                       __uint_as_float(r[q * 4 + 3]));
                *(float4*)(orow + col) = v;
            }
        }
    }

    __syncthreads();
    // keep SMEM/TMEM alive until the whole pair is done
    CLUSTER_ARRIVE();
    CLUSTER_WAIT();
    if (wid == 0) {
        asm volatile("tcgen05.dealloc.cta_group::2.sync.aligned.b32 %0, %1;"
                     :: "r"(tmem), "r"(512u));
    }
#endif // HAS_TCGEN05
}

// ---------------------------------------------------------------- launch
extern "C" void kernel_launch(void* const* d_in, const int* in_sizes, int n_in,
                              void* d_out, int out_size) {
    const float* inp = (const float*)d_in[0];
    const float* wgt = (const float*)d_in[1];
    if (n_in >= 2 && in_sizes[0] != (int)((size_t)M_ROWS * KDIM)) {
        const float* t = inp; inp = wgt; wgt = t;
    }
    float* out = (float*)d_out;

    cudaFuncSetAttribute(bgemm_kernel,
                         cudaFuncAttributeMaxDynamicSharedMemorySize,
                         SMEM_DYN_BYTES);

    const size_t nA8 = (size_t)M_ROWS * KDIM / 8;
    const size_t nW8 = (size_t)N_PAD * KDIM / 8;
    quantA_kernel<<<(unsigned)((nA8 + 255) / 256), 256>>>(inp);
    quantW_kernel<<<(unsigned)((nW8 + 255) / 256), 256>>>(wgt);

    // grid: x = 2 CTAs/cluster * 2 ntiles = 4, y = 32 mtiles -> 128 CTAs, 1 wave
    dim3 grid(4, M_ROWS / TILE_MP);
    bgemm_kernel<<<grid, THREADS, SMEM_DYN_BYTES>>>(out);
}